// round 14
// baseline (speedup 1.0000x reference)
#include <cuda_runtime.h>
#include <math.h>

// Problem dims (fixed by the reference)
#define Bsz 64
#define Tt  512
#define Dd  256
#define Hh  256
#define NT  512     // threads per CTA (16 warps)
#define NSL 8       // k-slices
#define KSL 32      // k per slice (NSL*KSL == 256)

__device__ __forceinline__ float sigm(float x) { return 1.0f / (1.0f + __expf(-x)); }

__device__ __forceinline__ void fma4(float4& a, float s, const float4 w) {
    a.x = fmaf(s, w.x, a.x);
    a.y = fmaf(s, w.y, a.y);
    a.z = fmaf(s, w.z, a.z);
    a.w = fmaf(s, w.w, a.w);
}

// One CTA per batch element. Persistent loop over timesteps; no inter-CTA
// communication except the final atomicAdd of the partial loss.
__global__ void __launch_bounds__(NT, 1) gru_seq_kernel(
    const float* __restrict__ x,      // [B, T, D]
    const int*   __restrict__ xlen,   // [B]
    const float* __restrict__ xlab,   // [B]
    const float* __restrict__ Wz,     // [L, D, H]
    const float* __restrict__ Uz,     // [L, H, H]
    const float* __restrict__ Wr,
    const float* __restrict__ Ur,
    const float* __restrict__ Wh,
    const float* __restrict__ Uh,
    const float* __restrict__ Wo,     // [H, 2]
    float* __restrict__ out)
{
    const int b = blockIdx.x;

    __shared__ __align__(16) float in0[Hh];        // x_t
    __shared__ __align__(16) float st0[Hh];        // layer-0 hidden (S1[0])
    __shared__ __align__(16) float st1[Hh];        // layer-1 hidden (S1[1])
    __shared__ __align__(16) float rs[Hh];         // r * S1 buffer
    __shared__ __align__(16) float pz[NSL][Hh];    // partial sums (z)
    __shared__ __align__(16) float pr[NSL][Hh];    // partial sums (r)
    __shared__ __align__(16) float ph[NSL][Hh];    // partial sums (h)
    __shared__ float red[NT / 32];

    const int tid = threadIdx.x;
    const int c4  = (tid & 63) << 2;   // 4 output columns per thread
    const int s   = tid >> 6;          // k-slice 0..7
    const int k0  = s * KSL;

    if (tid < Hh) { st0[tid] = 0.0f; st1[tid] = 0.0f; }

    const int   Tb  = xlen[b];
    const float lab = xlab[b];
    float loss = 0.0f;
    const float* xrow = x + (size_t)b * Tt * Dd;
    __syncthreads();

    for (int t = 0; t < Tb; ++t) {
        if (tid < Dd) in0[tid] = xrow[(size_t)t * Dd + tid];
        __syncthreads();

        #pragma unroll
        for (int l = 0; l < 2; ++l) {
            const float* inv = (l == 0) ? in0 : st0;   // layer input vector
            float*       stv = (l == 0) ? st0 : st1;   // layer hidden state
            const size_t off = (size_t)l * Dd * Hh;
            const float* wz = Wz + off; const float* uz = Uz + off;
            const float* wr = Wr + off; const float* ur = Ur + off;
            const float* wh = Wh + off; const float* uh = Uh + off;

            // ---- Phase A: z/r pre-activations + input part of h ----
            float4 az = make_float4(0.f, 0.f, 0.f, 0.f);
            float4 ar = az, ah = az;
            #pragma unroll 4
            for (int k = k0; k < k0 + KSL; ++k) {
                const float vi = inv[k];     // broadcast LDS
                const float vs = stv[k];
                const int o = k * Hh + c4;
                float4 w;
                w = *(const float4*)(wz + o); fma4(az, vi, w);
                w = *(const float4*)(uz + o); fma4(az, vs, w);
                w = *(const float4*)(wr + o); fma4(ar, vi, w);
                w = *(const float4*)(ur + o); fma4(ar, vs, w);
                w = *(const float4*)(wh + o); fma4(ah, vi, w);
            }
            *(float4*)&pz[s][c4] = az;
            *(float4*)&pr[s][c4] = ar;
            *(float4*)&ph[s][c4] = ah;
            __syncthreads();

            float zz = 0.f, rr = 0.f, hh = 0.f, sold = 0.f;
            if (tid < Hh) {
                #pragma unroll
                for (int q = 0; q < NSL; ++q) {
                    zz += pz[q][tid]; rr += pr[q][tid]; hh += ph[q][tid];
                }
                zz = sigm(zz);
                rr = sigm(rr);
                sold = stv[tid];
                rs[tid] = rr * sold;
            }
            __syncthreads();   // rs visible; ph free for reuse

            // ---- Phase B: (r*S1) @ Uh ----
            float4 a2 = make_float4(0.f, 0.f, 0.f, 0.f);
            #pragma unroll 4
            for (int k = k0; k < k0 + KSL; ++k) {
                const float v = rs[k];
                float4 w = *(const float4*)(uh + k * Hh + c4);
                fma4(a2, v, w);
            }
            *(float4*)&ph[s][c4] = a2;
            __syncthreads();

            if (tid < Hh) {
                float hp = hh;
                #pragma unroll
                for (int q = 0; q < NSL; ++q) hp += ph[q][tid];
                const float h  = tanhf(hp);
                const float hn = (1.0f - zz) * sold + zz * h;
                stv[tid] = hn;   // S2 dropped: it never affects the loss
            }
            __syncthreads();
        }

        // ---- score = sigmoid((h1 @ Wo)[:,1]); masked squared error ----
        float p = (tid < Hh) ? st1[tid] * Wo[tid * 2 + 1] : 0.0f;
        #pragma unroll
        for (int o2 = 16; o2 > 0; o2 >>= 1)
            p += __shfl_down_sync(0xffffffffu, p, o2);
        if ((tid & 31) == 0) red[tid >> 5] = p;
        __syncthreads();
        if (tid == 0) {
            float sum2 = 0.0f;
            #pragma unroll
            for (int w2 = 0; w2 < NT / 32; ++w2) sum2 += red[w2];
            const float sc = sigm(sum2);
            const float d  = lab - sc;
            loss += d * d;
        }
        __syncthreads();   // protect in0/red before next step
    }

    if (tid == 0) atomicAdd(out, loss);
}

extern "C" void kernel_launch(void* const* d_in, const int* in_sizes, int n_in,
                              void* d_out, int out_size)
{
    const float* x    = (const float*)d_in[0];
    const int*   xlen = (const int*)  d_in[1];
    const float* xlab = (const float*)d_in[2];
    const float* Wz   = (const float*)d_in[3];
    const float* Uz   = (const float*)d_in[4];
    const float* Wr   = (const float*)d_in[5];
    const float* Ur   = (const float*)d_in[6];
    const float* Wh   = (const float*)d_in[7];
    const float* Uh   = (const float*)d_in[8];
    const float* Wo   = (const float*)d_in[9];

    cudaMemsetAsync(d_out, 0, (size_t)out_size * sizeof(float));
    gru_seq_kernel<<<Bsz, NT>>>(x, xlen, xlab, Wz, Uz, Wr, Ur, Wh, Uh, Wo,
                                (float*)d_out);
}

// round 15
// speedup vs baseline: 1.0008x; 1.0008x over previous
#include <cuda_runtime.h>
#include <math.h>

// Problem dims (fixed by the reference)
#define Bsz 64
#define Tt  512
#define Dd  256
#define Hh  256
#define NT  512     // threads per CTA (16 warps)
#define NSL 8       // k-slices
#define KSL 32      // k per slice (NSL*KSL == 256)

__device__ __forceinline__ float sigm(float x) { return 1.0f / (1.0f + __expf(-x)); }

__device__ __forceinline__ void fma4(float4& a, float s, const float4 w) {
    a.x = fmaf(s, w.x, a.x);
    a.y = fmaf(s, w.y, a.y);
    a.z = fmaf(s, w.z, a.z);
    a.w = fmaf(s, w.w, a.w);
}

// One CTA per batch element. Persistent loop over timesteps; no inter-CTA
// communication except the final atomicAdd of the partial loss.
__global__ void __launch_bounds__(NT, 1) gru_seq_kernel(
    const float* __restrict__ x,      // [B, T, D]
    const int*   __restrict__ xlen,   // [B]
    const float* __restrict__ xlab,   // [B]
    const float* __restrict__ Wz,     // [L, D, H]
    const float* __restrict__ Uz,     // [L, H, H]
    const float* __restrict__ Wr,
    const float* __restrict__ Ur,
    const float* __restrict__ Wh,
    const float* __restrict__ Uh,
    const float* __restrict__ Wo,     // [H, 2]
    float* __restrict__ out)
{
    const int b = blockIdx.x;

    __shared__ __align__(16) float in0[Hh];        // x_t
    __shared__ __align__(16) float st0[Hh];        // layer-0 hidden (S1[0])
    __shared__ __align__(16) float st1[Hh];        // layer-1 hidden (S1[1])
    __shared__ __align__(16) float rs[Hh];         // r * S1 buffer
    __shared__ __align__(16) float pz[NSL][Hh];    // partial sums (z)
    __shared__ __align__(16) float pr[NSL][Hh];    // partial sums (r)
    __shared__ __align__(16) float ph[NSL][Hh];    // partial sums (h)
    __shared__ float red[NT / 32];

    const int tid = threadIdx.x;
    const int c4  = (tid & 63) << 2;   // 4 output columns per thread
    const int s   = tid >> 6;          // k-slice 0..7
    const int k0  = s * KSL;

    if (tid < Hh) { st0[tid] = 0.0f; st1[tid] = 0.0f; }

    const int   Tb  = xlen[b];
    const float lab = xlab[b];
    float loss = 0.0f;
    const float* xrow = x + (size_t)b * Tt * Dd;
    __syncthreads();

    for (int t = 0; t < Tb; ++t) {
        if (tid < Dd) in0[tid] = xrow[(size_t)t * Dd + tid];
        __syncthreads();

        #pragma unroll
        for (int l = 0; l < 2; ++l) {
            const float* inv = (l == 0) ? in0 : st0;   // layer input vector
            float*       stv = (l == 0) ? st0 : st1;   // layer hidden state
            const size_t off = (size_t)l * Dd * Hh;
            const float* wz = Wz + off; const float* uz = Uz + off;
            const float* wr = Wr + off; const float* ur = Ur + off;
            const float* wh = Wh + off; const float* uh = Uh + off;

            // ---- Phase A: z/r pre-activations + input part of h ----
            float4 az = make_float4(0.f, 0.f, 0.f, 0.f);
            float4 ar = az, ah = az;
            #pragma unroll 4
            for (int k = k0; k < k0 + KSL; ++k) {
                const float vi = inv[k];     // broadcast LDS
                const float vs = stv[k];
                const int o = k * Hh + c4;
                float4 w;
                w = *(const float4*)(wz + o); fma4(az, vi, w);
                w = *(const float4*)(uz + o); fma4(az, vs, w);
                w = *(const float4*)(wr + o); fma4(ar, vi, w);
                w = *(const float4*)(ur + o); fma4(ar, vs, w);
                w = *(const float4*)(wh + o); fma4(ah, vi, w);
            }
            *(float4*)&pz[s][c4] = az;
            *(float4*)&pr[s][c4] = ar;
            *(float4*)&ph[s][c4] = ah;
            __syncthreads();

            float zz = 0.f, rr = 0.f, hh = 0.f, sold = 0.f;
            if (tid < Hh) {
                #pragma unroll
                for (int q = 0; q < NSL; ++q) {
                    zz += pz[q][tid]; rr += pr[q][tid]; hh += ph[q][tid];
                }
                zz = sigm(zz);
                rr = sigm(rr);
                sold = stv[tid];
                rs[tid] = rr * sold;
            }
            __syncthreads();   // rs visible; ph free for reuse

            // ---- Phase B: (r*S1) @ Uh ----
            float4 a2 = make_float4(0.f, 0.f, 0.f, 0.f);
            #pragma unroll 4
            for (int k = k0; k < k0 + KSL; ++k) {
                const float v = rs[k];
                float4 w = *(const float4*)(uh + k * Hh + c4);
                fma4(a2, v, w);
            }
            *(float4*)&ph[s][c4] = a2;
            __syncthreads();

            if (tid < Hh) {
                float hp = hh;
                #pragma unroll
                for (int q = 0; q < NSL; ++q) hp += ph[q][tid];
                const float h  = tanhf(hp);
                const float hn = (1.0f - zz) * sold + zz * h;
                stv[tid] = hn;   // S2 dropped: it never affects the loss
            }
            __syncthreads();
        }

        // ---- score = sigmoid((h1 @ Wo)[:,1]); masked squared error ----
        float p = (tid < Hh) ? st1[tid] * Wo[tid * 2 + 1] : 0.0f;
        #pragma unroll
        for (int o2 = 16; o2 > 0; o2 >>= 1)
            p += __shfl_down_sync(0xffffffffu, p, o2);
        if ((tid & 31) == 0) red[tid >> 5] = p;
        __syncthreads();
        if (tid == 0) {
            float sum2 = 0.0f;
            #pragma unroll
            for (int w2 = 0; w2 < NT / 32; ++w2) sum2 += red[w2];
            const float sc = sigm(sum2);
            const float d  = lab - sc;
            loss += d * d;
        }
        __syncthreads();   // protect in0/red before next step
    }

    if (tid == 0) atomicAdd(out, loss);
}

extern "C" void kernel_launch(void* const* d_in, const int* in_sizes, int n_in,
                              void* d_out, int out_size)
{
    const float* x    = (const float*)d_in[0];
    const int*   xlen = (const int*)  d_in[1];
    const float* xlab = (const float*)d_in[2];
    const float* Wz   = (const float*)d_in[3];
    const float* Uz   = (const float*)d_in[4];
    const float* Wr   = (const float*)d_in[5];
    const float* Ur   = (const float*)d_in[6];
    const float* Wh   = (const float*)d_in[7];
    const float* Uh   = (const float*)d_in[8];
    const float* Wo   = (const float*)d_in[9];

    cudaMemsetAsync(d_out, 0, (size_t)out_size * sizeof(float));
    gru_seq_kernel<<<Bsz, NT>>>(x, xlen, xlab, Wz, Uz, Wr, Ur, Wh, Uh, Wo,
                                (float*)d_out);
}

// round 16
// speedup vs baseline: 1.0857x; 1.0848x over previous
#include <cuda_runtime.h>
#include <math.h>
#include <stdint.h>

// Problem dims (fixed by the reference)
#define Bsz 64
#define Tt  512
#define Dd  256
#define Hh  256

// Decomposition: 16 clusters x 8 CTAs. Each cluster owns GRP=4 batch rows;
// each CTA owns CP=32 output columns (full k-range) of every gate.
#define CLS 8          // CTAs per cluster (column split)
#define GRP 4          // batch rows per cluster
#define CP  32         // output columns per CTA
#define NT  256        // threads per CTA (8 warps)
#define PAD 264        // padded row stride (words) for activation arrays (bank-conflict-free)

__device__ __forceinline__ float sigm(float x) { return 1.0f / (1.0f + __expf(-x)); }

__device__ __forceinline__ void fma4(float4& a, float s, const float4 w) {
    a.x = fmaf(s, w.x, a.x);
    a.y = fmaf(s, w.y, a.y);
    a.z = fmaf(s, w.z, a.z);
    a.w = fmaf(s, w.w, a.w);
}

__device__ __forceinline__ uint32_t smem_u32(const void* p) {
    return (uint32_t)__cvta_generic_to_shared(p);
}

// Store one float into the same smem offset of cluster CTA `rank`.
__device__ __forceinline__ void st_cluster(uint32_t laddr, uint32_t rank, float v) {
    uint32_t raddr;
    asm volatile("mapa.shared::cluster.u32 %0, %1, %2;" : "=r"(raddr) : "r"(laddr), "r"(rank));
    asm volatile("st.shared::cluster.f32 [%0], %1;" :: "r"(raddr), "f"(v) : "memory");
}

#define CLUSTER_SYNC() do { \
    asm volatile("barrier.cluster.arrive.aligned;" ::: "memory"); \
    asm volatile("barrier.cluster.wait.aligned;"   ::: "memory"); } while (0)

__global__ void __launch_bounds__(NT, 1) __cluster_dims__(CLS, 1, 1)
gru_cluster_kernel(
    const float* __restrict__ x,      // [B, T, D]
    const int*   __restrict__ xlen,   // [B]
    const float* __restrict__ xlab,   // [B]
    const float* __restrict__ Wz,     // [L, D, H]
    const float* __restrict__ Uz,     // [L, H, H]
    const float* __restrict__ Wr,
    const float* __restrict__ Ur,
    const float* __restrict__ Wh,
    const float* __restrict__ Uh,
    const float* __restrict__ Wo,     // [H, 2]
    float* __restrict__ out)
{
    const int cid  = blockIdx.x / CLS;       // cluster id -> batch group
    const int rank = blockIdx.x % CLS;       // column slice
    const int b0   = cid * GRP;

    // Replicated activation vectors (each CTA holds the full 256-wide copies)
    __shared__ __align__(16) float in0[GRP][PAD];   // x_t
    __shared__ __align__(16) float s0 [GRP][PAD];   // layer-0 hidden
    __shared__ __align__(16) float s1 [GRP][PAD];   // layer-1 hidden
    __shared__ __align__(16) float rsv[GRP][PAD];   // r * S1 (assembled via DSMEM)
    // k-slice partial sums: [gate][warp][row][col]
    __shared__ __align__(16) float psum[3][8][GRP][CP];
    __shared__ float zbuf[GRP][CP];
    __shared__ float hinbuf[GRP][CP];
    __shared__ float wo1[Hh];

    const int tid  = threadIdx.x;
    const int w    = tid >> 5;                 // warp -> k-slice of 32
    const int row  = (tid >> 3) & 3;           // batch row within group
    const int cg   = tid & 7;                  // column group (4 cols)
    const int kb   = w * 32;
    const int gc   = rank * CP + cg * 4;       // global output column base

    // ---- init ----
    float* s0f = &s0[0][0];
    float* s1f = &s1[0][0];
    float* rsf = &rsv[0][0];
    for (int i = tid; i < GRP * PAD; i += NT) { s0f[i] = 0.f; s1f[i] = 0.f; rsf[i] = 0.f; }
    if (tid < Hh) wo1[tid] = Wo[2 * tid + 1];

    // sequence bookkeeping
    int Tmax = 0;
    #pragma unroll
    for (int r = 0; r < GRP; ++r) {
        int lr = xlen[b0 + r];
        Tmax = lr > Tmax ? lr : Tmax;
    }
    int   mylen = 0;
    float mylab = 0.f;
    float lossr = 0.f;
    if (rank == 0 && tid < 128 && (tid & 31) == 0) {
        mylen = xlen[b0 + (tid >> 5)];
        mylab = xlab[b0 + (tid >> 5)];
    }
    __syncthreads();
    CLUSTER_SYNC();

    for (int t = 0; t < Tmax; ++t) {
        // load x_t for the 4 rows (replicated per CTA)
        {
            const int r   = tid >> 6;
            const int c4i = (tid & 63) << 2;
            const float4 v = *(const float4*)(x + (((size_t)(b0 + r) * Tt + t) * Dd + c4i));
            *(float4*)&in0[r][c4i] = v;
        }
        __syncthreads();

        #pragma unroll
        for (int l = 0; l < 2; ++l) {
            const float* inv = (l == 0) ? &in0[0][0] : &s0[0][0];
            float*       stv = (l == 0) ? &s0[0][0]  : &s1[0][0];
            const size_t off = (size_t)l * Dd * Hh;
            const float* wz = Wz + off + gc;
            const float* uz = Uz + off + gc;
            const float* wr = Wr + off + gc;
            const float* ur = Ur + off + gc;
            const float* wh = Wh + off + gc;
            const float* uh = Uh + off + gc;

            // ---- Phase A: z/r pre-activations + input part of h ----
            float4 az = make_float4(0.f, 0.f, 0.f, 0.f);
            float4 ar = az, ah = az;
            #pragma unroll 4
            for (int kk = 0; kk < 32; ++kk) {
                const int k = kb + kk;
                const float  vi = inv[row * PAD + k];
                const float  vs = stv[row * PAD + k];
                const size_t o  = (size_t)k * Hh;
                float4 wv;
                wv = *(const float4*)(wz + o); fma4(az, vi, wv);
                wv = *(const float4*)(uz + o); fma4(az, vs, wv);
                wv = *(const float4*)(wr + o); fma4(ar, vi, wv);
                wv = *(const float4*)(ur + o); fma4(ar, vs, wv);
                wv = *(const float4*)(wh + o); fma4(ah, vi, wv);
            }
            *(float4*)&psum[0][w][row][cg * 4] = az;
            *(float4*)&psum[1][w][row][cg * 4] = ar;
            *(float4*)&psum[2][w][row][cg * 4] = ah;
            __syncthreads();

            // ---- Reduce A: 384 outputs (z, r, h-in), each 8 partials ----
            {
                int o = tid;
                #pragma unroll
                for (int pass = 0; pass < 2; ++pass, o += NT) {
                    if (o < 384) {
                        const int g = o >> 7, rc = o & 127, r = rc >> 5, c = rc & 31;
                        float v = 0.f;
                        #pragma unroll
                        for (int q = 0; q < 8; ++q) v += psum[g][q][r][c];
                        if (g == 0) {
                            zbuf[r][c] = sigm(v);
                        } else if (g == 2) {
                            hinbuf[r][c] = v;
                        } else {
                            const float sold = stv[r * PAD + rank * CP + c];
                            const float rs   = sigm(v) * sold;
                            const uint32_t la = smem_u32(&rsv[r][rank * CP + c]);
                            #pragma unroll
                            for (uint32_t q = 0; q < CLS; ++q) st_cluster(la, q, rs);
                        }
                    }
                }
            }
            CLUSTER_SYNC();   // rsv fully assembled in every CTA

            // ---- Phase B: (r*S1) @ Uh for our column slice ----
            float4 a2 = make_float4(0.f, 0.f, 0.f, 0.f);
            #pragma unroll 4
            for (int kk = 0; kk < 32; ++kk) {
                const int k = kb + kk;
                const float  v = rsv[row][k];
                const float4 u = *(const float4*)(uh + (size_t)k * Hh);
                fma4(a2, v, u);
            }
            *(float4*)&psum[0][w][row][cg * 4] = a2;
            __syncthreads();

            if (tid < GRP * CP) {
                const int r = tid >> 5, c = tid & 31;
                float hp = hinbuf[r][c];
                #pragma unroll
                for (int q = 0; q < 8; ++q) hp += psum[0][q][r][c];
                const float h    = tanhf(hp);
                const float z    = zbuf[r][c];
                const float sold = stv[r * PAD + rank * CP + c];
                const float hn   = (1.0f - z) * sold + z * h;   // S2 dropped (unused)
                const uint32_t la = smem_u32(&stv[r * PAD + rank * CP + c]);
                #pragma unroll
                for (uint32_t q = 0; q < CLS; ++q) st_cluster(la, q, hn);
            }
            CLUSTER_SYNC();   // new hidden state visible cluster-wide
        }

        // ---- score = sigmoid((h1 @ Wo)[:,1]); masked squared error ----
        if (rank == 0 && tid < 128) {
            const int r  = tid >> 5, ln = tid & 31;
            const float* s1r = &s1[0][0] + r * PAD;
            float p = 0.f;
            #pragma unroll
            for (int j = 0; j < 8; ++j) {
                const int k = ln * 8 + j;
                p += s1r[k] * wo1[k];
            }
            #pragma unroll
            for (int o2 = 16; o2 > 0; o2 >>= 1)
                p += __shfl_down_sync(0xffffffffu, p, o2);
            if (ln == 0 && t < mylen) {
                const float d = mylab - sigm(p);
                lossr += d * d;
            }
        }
        // no extra barrier needed: in0 rewrite next step is fenced by __syncthreads
    }

    if (rank == 0 && tid < 128 && (tid & 31) == 0)
        atomicAdd(out, lossr);
}

extern "C" void kernel_launch(void* const* d_in, const int* in_sizes, int n_in,
                              void* d_out, int out_size)
{
    const float* x    = (const float*)d_in[0];
    const int*   xlen = (const int*)  d_in[1];
    const float* xlab = (const float*)d_in[2];
    const float* Wz   = (const float*)d_in[3];
    const float* Uz   = (const float*)d_in[4];
    const float* Wr   = (const float*)d_in[5];
    const float* Ur   = (const float*)d_in[6];
    const float* Wh   = (const float*)d_in[7];
    const float* Uh   = (const float*)d_in[8];
    const float* Wo   = (const float*)d_in[9];

    cudaMemsetAsync(d_out, 0, (size_t)out_size * sizeof(float));
    gru_cluster_kernel<<<(Bsz / GRP) * CLS, NT>>>(x, xlen, xlab,
                                                  Wz, Uz, Wr, Ur, Wh, Uh, Wo,
                                                  (float*)d_out);
}

// round 17
// speedup vs baseline: 1.8123x; 1.6693x over previous
#include <cuda_runtime.h>
#include <math.h>
#include <stdint.h>

// Problem dims (fixed by the reference)
#define Bsz 64
#define Tt  512
#define Dd  256
#define Hh  256

// Decomposition: 16 clusters x 8 CTAs. Cluster owns GRP=4 batch rows;
// CTA owns CP=32 output columns. Thread = (k-slice of KS, col-group of 4);
// rows are iterated in registers so each weight load feeds 4 rows.
#define CLS 8
#define GRP 4
#define CP  32
#define NT  256
#define NS  32        // k-slices
#define KS  8         // k per slice (NS*KS == 256)

__device__ __forceinline__ float sigm(float x) { return 1.0f / (1.0f + __expf(-x)); }

__device__ __forceinline__ void fma2(unsigned long long& d,
                                     unsigned long long a,
                                     unsigned long long b) {
    asm("fma.rn.f32x2 %0, %1, %2, %0;" : "+l"(d) : "l"(a), "l"(b));
}

__device__ __forceinline__ unsigned long long ld_pair(const float2* p) {
    return *reinterpret_cast<const unsigned long long*>(p);
}

__device__ __forceinline__ uint32_t smem_u32(const void* p) {
    return (uint32_t)__cvta_generic_to_shared(p);
}

// 16B store into the same smem offset of cluster CTA `rank`.
__device__ __forceinline__ void st_cluster128(uint32_t laddr, uint32_t rank,
                                              float a, float b, float c, float d) {
    uint32_t raddr;
    asm volatile("mapa.shared::cluster.u32 %0, %1, %2;" : "=r"(raddr) : "r"(laddr), "r"(rank));
    asm volatile("st.shared::cluster.v4.f32 [%0], {%1,%2,%3,%4};"
                 :: "r"(raddr), "f"(a), "f"(b), "f"(c), "f"(d) : "memory");
}

#define CLUSTER_SYNC() do { \
    asm volatile("barrier.cluster.arrive.aligned;" ::: "memory"); \
    asm volatile("barrier.cluster.wait.aligned;"   ::: "memory"); } while (0)

struct __align__(16) Smem {
    float2 in0d[GRP * Hh];                 // x_t, duplicated (v,v)
    float2 s0d [GRP * Hh];                 // layer-0 hidden, dup
    float2 s1d [GRP * Hh];                 // layer-1 hidden, dup
    float2 rsd [GRP * Hh];                 // r * S1, dup
    unsigned long long psum[3][NS][GRP][CP / 2];  // packed partial sums
    float zbuf[GRP][CP];
    float hinbuf[GRP][CP];
    float wo1[Hh];
};

__global__ void __launch_bounds__(NT, 1) __cluster_dims__(CLS, 1, 1)
gru_cluster2_kernel(
    const float* __restrict__ x,      // [B, T, D]
    const int*   __restrict__ xlen,   // [B]
    const float* __restrict__ xlab,   // [B]
    const float* __restrict__ Wz, const float* __restrict__ Uz,
    const float* __restrict__ Wr, const float* __restrict__ Ur,
    const float* __restrict__ Wh, const float* __restrict__ Uh,
    const float* __restrict__ Wo,    // [H, 2]
    float* __restrict__ out)
{
    extern __shared__ __align__(16) char smem_raw[];
    Smem& sm = *reinterpret_cast<Smem*>(smem_raw);

    const int cid  = blockIdx.x / CLS;
    const int rank = blockIdx.x % CLS;
    const int b0   = cid * GRP;

    const int tid = threadIdx.x;
    const int w   = tid >> 3;            // k-slice 0..31
    const int cg  = tid & 7;             // col group (4 cols)
    const int kb  = w * KS;
    const int gc  = rank * CP + cg * 4;  // global output column base

    // ---- init ----
    for (int i = tid; i < GRP * Hh; i += NT) {
        sm.s0d[i] = make_float2(0.f, 0.f);
        sm.s1d[i] = make_float2(0.f, 0.f);
        sm.rsd[i] = make_float2(0.f, 0.f);
    }
    sm.wo1[tid] = Wo[2 * tid + 1];

    int Tmax = 0;
    #pragma unroll
    for (int r = 0; r < GRP; ++r) {
        int lr = xlen[b0 + r];
        Tmax = lr > Tmax ? lr : Tmax;
    }
    int   mylen = 0;
    float mylab = 0.f;
    float lossr = 0.f;
    if (rank == 0 && tid < 128 && (tid & 31) == 0) {
        mylen = xlen[b0 + (tid >> 5)];
        mylab = xlab[b0 + (tid >> 5)];
    }
    __syncthreads();
    CLUSTER_SYNC();

    for (int t = 0; t < Tmax; ++t) {
        // load x_t for the 4 rows, duplicated
        {
            const int r   = tid >> 6;
            const int c4i = (tid & 63) << 2;
            const float4 v = *(const float4*)(x + (((size_t)(b0 + r) * Tt + t) * Dd + c4i));
            sm.in0d[r * Hh + c4i + 0] = make_float2(v.x, v.x);
            sm.in0d[r * Hh + c4i + 1] = make_float2(v.y, v.y);
            sm.in0d[r * Hh + c4i + 2] = make_float2(v.z, v.z);
            sm.in0d[r * Hh + c4i + 3] = make_float2(v.w, v.w);
        }
        __syncthreads();

        #pragma unroll
        for (int l = 0; l < 2; ++l) {
            const float2* invd = (l == 0) ? sm.in0d : sm.s0d;
            float2*       stvd = (l == 0) ? sm.s0d  : sm.s1d;
            const size_t off = (size_t)l * Dd * Hh + gc;
            const float* wz = Wz + off; const float* uz = Uz + off;
            const float* wr = Wr + off; const float* ur = Ur + off;
            const float* wh = Wh + off; const float* uh = Uh + off;

            // ---- Phase A: z/r pre-activations + input part of h ----
            unsigned long long az[GRP][2], ag[GRP][2], ah[GRP][2];
            #pragma unroll
            for (int r = 0; r < GRP; ++r) {
                az[r][0] = az[r][1] = 0ull;
                ag[r][0] = ag[r][1] = 0ull;
                ah[r][0] = ah[r][1] = 0ull;
            }
            #pragma unroll
            for (int kk = 0; kk < KS; ++kk) {
                const int k = kb + kk;
                const size_t o = (size_t)k * Hh;
                const ulonglong2 wzv = *(const ulonglong2*)(wz + o);
                const ulonglong2 uzv = *(const ulonglong2*)(uz + o);
                const ulonglong2 wrv = *(const ulonglong2*)(wr + o);
                const ulonglong2 urv = *(const ulonglong2*)(ur + o);
                const ulonglong2 whv = *(const ulonglong2*)(wh + o);
                #pragma unroll
                for (int r = 0; r < GRP; ++r) {
                    const unsigned long long vi = ld_pair(&invd[r * Hh + k]);
                    const unsigned long long vs = ld_pair(&stvd[r * Hh + k]);
                    fma2(az[r][0], vi, wzv.x); fma2(az[r][1], vi, wzv.y);
                    fma2(az[r][0], vs, uzv.x); fma2(az[r][1], vs, uzv.y);
                    fma2(ag[r][0], vi, wrv.x); fma2(ag[r][1], vi, wrv.y);
                    fma2(ag[r][0], vs, urv.x); fma2(ag[r][1], vs, urv.y);
                    fma2(ah[r][0], vi, whv.x); fma2(ah[r][1], vi, whv.y);
                }
            }
            #pragma unroll
            for (int r = 0; r < GRP; ++r) {
                *(ulonglong2*)&sm.psum[0][w][r][cg * 2] = make_ulonglong2(az[r][0], az[r][1]);
                *(ulonglong2*)&sm.psum[1][w][r][cg * 2] = make_ulonglong2(ag[r][0], ag[r][1]);
                *(ulonglong2*)&sm.psum[2][w][r][cg * 2] = make_ulonglong2(ah[r][0], ah[r][1]);
            }
            __syncthreads();

            // ---- Reduce A: 192 packed outputs (z, r, h-in), 32 partials each ----
            if (tid < 192) {
                const int g  = tid >> 6;
                const int r  = (tid >> 4) & 3;
                const int pc = tid & 15;            // pair-column 0..15 (cols pc*2, pc*2+1)
                float2 s0v = make_float2(0.f, 0.f), s1v = s0v, s2v = s0v, s3v = s0v;
                #pragma unroll
                for (int q = 0; q < NS; q += 4) {
                    const float2 a0 = *(const float2*)&sm.psum[g][q + 0][r][pc];
                    const float2 a1 = *(const float2*)&sm.psum[g][q + 1][r][pc];
                    const float2 a2 = *(const float2*)&sm.psum[g][q + 2][r][pc];
                    const float2 a3 = *(const float2*)&sm.psum[g][q + 3][r][pc];
                    s0v.x += a0.x; s0v.y += a0.y;
                    s1v.x += a1.x; s1v.y += a1.y;
                    s2v.x += a2.x; s2v.y += a2.y;
                    s3v.x += a3.x; s3v.y += a3.y;
                }
                const float v0 = s0v.x + s1v.x + s2v.x + s3v.x;
                const float v1 = s0v.y + s1v.y + s2v.y + s3v.y;
                const int lc = pc * 2;               // local col in [0, CP)
                if (g == 0) {
                    sm.zbuf[r][lc] = sigm(v0);
                    sm.zbuf[r][lc + 1] = sigm(v1);
                } else if (g == 2) {
                    sm.hinbuf[r][lc] = v0;
                    sm.hinbuf[r][lc + 1] = v1;
                } else {
                    const int gcol = rank * CP + lc;
                    const float sold0 = stvd[r * Hh + gcol].x;
                    const float sold1 = stvd[r * Hh + gcol + 1].x;
                    const float rs0 = sigm(v0) * sold0;
                    const float rs1 = sigm(v1) * sold1;
                    const uint32_t la = smem_u32(&sm.rsd[r * Hh + gcol]);
                    #pragma unroll
                    for (uint32_t q = 0; q < CLS; ++q)
                        st_cluster128(la, q, rs0, rs0, rs1, rs1);
                }
            }
            CLUSTER_SYNC();   // rsd fully assembled in every CTA

            // ---- Phase B: (r*S1) @ Uh for our column slice ----
            unsigned long long a2p[GRP][2];
            #pragma unroll
            for (int r = 0; r < GRP; ++r) a2p[r][0] = a2p[r][1] = 0ull;
            #pragma unroll
            for (int kk = 0; kk < KS; ++kk) {
                const int k = kb + kk;
                const ulonglong2 uv = *(const ulonglong2*)(uh + (size_t)k * Hh);
                #pragma unroll
                for (int r = 0; r < GRP; ++r) {
                    const unsigned long long v = ld_pair(&sm.rsd[r * Hh + k]);
                    fma2(a2p[r][0], v, uv.x); fma2(a2p[r][1], v, uv.y);
                }
            }
            #pragma unroll
            for (int r = 0; r < GRP; ++r)
                *(ulonglong2*)&sm.psum[0][w][r][cg * 2] = make_ulonglong2(a2p[r][0], a2p[r][1]);
            __syncthreads();

            // ---- Reduce B + state update ----
            if (tid < 64) {
                const int r  = tid >> 4;
                const int pc = tid & 15;
                float2 s0v = make_float2(0.f, 0.f), s1v = s0v, s2v = s0v, s3v = s0v;
                #pragma unroll
                for (int q = 0; q < NS; q += 4) {
                    const float2 a0 = *(const float2*)&sm.psum[0][q + 0][r][pc];
                    const float2 a1 = *(const float2*)&sm.psum[0][q + 1][r][pc];
                    const float2 a2 = *(const float2*)&sm.psum[0][q + 2][r][pc];
                    const float2 a3 = *(const float2*)&sm.psum[0][q + 3][r][pc];
                    s0v.x += a0.x; s0v.y += a0.y;
                    s1v.x += a1.x; s1v.y += a1.y;
                    s2v.x += a2.x; s2v.y += a2.y;
                    s3v.x += a3.x; s3v.y += a3.y;
                }
                const int lc = pc * 2;
                const int gcol = rank * CP + lc;
                const float h0 = tanhf(sm.hinbuf[r][lc]     + s0v.x + s1v.x + s2v.x + s3v.x);
                const float h1 = tanhf(sm.hinbuf[r][lc + 1] + s0v.y + s1v.y + s2v.y + s3v.y);
                const float z0 = sm.zbuf[r][lc];
                const float z1 = sm.zbuf[r][lc + 1];
                const float so0 = stvd[r * Hh + gcol].x;
                const float so1 = stvd[r * Hh + gcol + 1].x;
                const float hn0 = (1.0f - z0) * so0 + z0 * h0;   // S2 dropped (unused)
                const float hn1 = (1.0f - z1) * so1 + z1 * h1;
                const uint32_t la = smem_u32(&stvd[r * Hh + gcol]);
                #pragma unroll
                for (uint32_t q = 0; q < CLS; ++q)
                    st_cluster128(la, q, hn0, hn0, hn1, hn1);
            }
            CLUSTER_SYNC();   // new hidden state visible cluster-wide
        }

        // ---- score = sigmoid((h1 @ Wo)[:,1]); masked squared error ----
        if (rank == 0 && tid < 128) {
            const int r = tid >> 5, ln = tid & 31;
            float p = 0.f;
            #pragma unroll
            for (int j = 0; j < 8; ++j) {
                const int k = ln * 8 + j;
                p += sm.s1d[r * Hh + k].x * sm.wo1[k];
            }
            #pragma unroll
            for (int o2 = 16; o2 > 0; o2 >>= 1)
                p += __shfl_down_sync(0xffffffffu, p, o2);
            if (ln == 0 && t < mylen) {
                const float d = mylab - sigm(p);
                lossr += d * d;
            }
        }
        // in0d rewrite next step is fenced by the __syncthreads at loop top
        __syncthreads();
    }

    if (rank == 0 && tid < 128 && (tid & 31) == 0)
        atomicAdd(out, lossr);
}

extern "C" void kernel_launch(void* const* d_in, const int* in_sizes, int n_in,
                              void* d_out, int out_size)
{
    const float* x    = (const float*)d_in[0];
    const int*   xlen = (const int*)  d_in[1];
    const float* xlab = (const float*)d_in[2];
    const float* Wz   = (const float*)d_in[3];
    const float* Uz   = (const float*)d_in[4];
    const float* Wr   = (const float*)d_in[5];
    const float* Ur   = (const float*)d_in[6];
    const float* Wh   = (const float*)d_in[7];
    const float* Uh   = (const float*)d_in[8];
    const float* Wo   = (const float*)d_in[9];

    static int smem_set = 0;
    if (!smem_set) {
        cudaFuncSetAttribute(gru_cluster2_kernel,
                             cudaFuncAttributeMaxDynamicSharedMemorySize,
                             (int)sizeof(Smem));
        smem_set = 1;
    }

    cudaMemsetAsync(d_out, 0, (size_t)out_size * sizeof(float));
    gru_cluster2_kernel<<<(Bsz / GRP) * CLS, NT, sizeof(Smem)>>>(
        x, xlen, xlab, Wz, Uz, Wr, Ur, Wh, Uh, Wo, (float*)d_out);
}